// round 1
// baseline (speedup 1.0000x reference)
#include <cuda_runtime.h>
#include <math.h>

// ---------------------------------------------------------------------------
// VAE_Gumbel: B=4096, D=5000, H=512, Z=64, K=50, T=0.1
// Pipeline: GEMM -> BN+ReLU -> GEMM(+gumbel) -> 50-iter softmax topk ->
//           4x encoder GEMM (leaky) -> mean/logvar GEMM -> reparam ->
//           decoder GEMMs (leaky, sigmoid)
// ---------------------------------------------------------------------------

#define BM 128
#define BN 128
#define BK 8
#define TM 8
#define TN 8

enum { EPI_NONE = 0, EPI_LEAKY = 2, EPI_SIGMOID = 3 };

// Scratch (static device globals; no runtime allocation allowed)
__device__ float g_h  [4096u * 512];    // weight_creator hidden (in-place BN+ReLU)
__device__ float g_w  [4096u * 5000];   // pre-gumbel logits
__device__ float g_xm [4096u * 5000];   // x * subset
__device__ float g_h1 [4096u * 1024];   // encoder h1
__device__ float g_h2 [4096u * 512];    // encoder h2 / h4
__device__ float g_h3 [4096u * 512];    // encoder h3
__device__ float g_z  [4096u * 64];     // latent sample
__device__ float g_dh [4096u * 1024];   // decoder hidden
__device__ float g_mean[512];
__device__ float g_rstd[512];

// ---------------------------------------------------------------------------
// Classic 128x128x8 register-tiled fp32 SGEMM, row-major A[M,K], B[K,N].
// C = act(A@B + bias). Requires K % 8 == 0, N % 4 == 0, M % 128 == 0
// (true for every GEMM in this net: K in {5000,1024,512,64}, N in
// {5000,1024,512,64}, M = 4096).
// ---------------------------------------------------------------------------
template <int EPI>
__global__ __launch_bounds__(256, 2)
void sgemm_kernel(const float* __restrict__ A, const float* __restrict__ B,
                  const float* __restrict__ bias, float* __restrict__ C,
                  int M, int N, int K)
{
    __shared__ float As[BK][BM];
    __shared__ float Bs[BK][BN];

    const int tid  = threadIdx.x;
    const int row0 = blockIdx.y * BM;
    const int col0 = blockIdx.x * BN;

    // A tile load mapping: BM*BK = 1024 floats = 256 float4
    const int aRow = tid >> 1;          // 0..127
    const int aCol = (tid & 1) << 2;    // 0 or 4
    // B tile load mapping: BK*BN = 1024 floats = 256 float4
    const int bRow = tid >> 5;          // 0..7
    const int bCol = (tid & 31) << 2;   // 0..124

    const int tx = tid & 15;
    const int ty = tid >> 4;
    const int mBase = ty * TM;
    const int nBase = tx * TN;

    float acc[TM][TN];
#pragma unroll
    for (int i = 0; i < TM; i++)
#pragma unroll
        for (int j = 0; j < TN; j++) acc[i][j] = 0.f;

    const float* Aptr = A + (size_t)(row0 + aRow) * K + aCol;
    const bool bvalid = (col0 + bCol) < N;   // N%4==0 so float4 is all-in or all-out

    for (int kt = 0; kt < K; kt += BK) {
        float4 a4 = *(const float4*)(Aptr + kt);
        float4 b4 = make_float4(0.f, 0.f, 0.f, 0.f);
        if (bvalid)
            b4 = *(const float4*)(B + (size_t)(kt + bRow) * N + col0 + bCol);

        __syncthreads();
        As[aCol + 0][aRow] = a4.x;
        As[aCol + 1][aRow] = a4.y;
        As[aCol + 2][aRow] = a4.z;
        As[aCol + 3][aRow] = a4.w;
        *(float4*)&Bs[bRow][bCol] = b4;
        __syncthreads();

#pragma unroll
        for (int kk = 0; kk < BK; kk++) {
            float a[TM], b[TN];
            *(float4*)&a[0] = *(const float4*)&As[kk][mBase];
            *(float4*)&a[4] = *(const float4*)&As[kk][mBase + 4];
            *(float4*)&b[0] = *(const float4*)&Bs[kk][nBase];
            *(float4*)&b[4] = *(const float4*)&Bs[kk][nBase + 4];
#pragma unroll
            for (int i = 0; i < TM; i++)
#pragma unroll
                for (int j = 0; j < TN; j++)
                    acc[i][j] = fmaf(a[i], b[j], acc[i][j]);
        }
    }

#pragma unroll
    for (int i = 0; i < TM; i++) {
        const int r = row0 + mBase + i;   // M % 128 == 0 -> always < M
#pragma unroll
        for (int j = 0; j < TN; j++) {
            const int c = col0 + nBase + j;
            if (c < N) {
                float v = acc[i][j] + bias[c];
                if (EPI == EPI_LEAKY)   v = v > 0.f ? v : 0.01f * v;
                if (EPI == EPI_SIGMOID) v = 1.0f / (1.0f + __expf(-v));
                C[(size_t)r * N + c] = v;
            }
        }
    }
}

// ---------------------------------------------------------------------------
// BatchNorm1d training-mode column stats over [4096, 512]
// ---------------------------------------------------------------------------
__global__ void bn_stats_kernel(const float* __restrict__ h,
                                float* __restrict__ mean, float* __restrict__ rstd)
{
    const int col = blockIdx.x * 32 + threadIdx.x;
    float s = 0.f, s2 = 0.f;
    for (int r = threadIdx.y; r < 4096; r += 8) {
        float v = h[(size_t)r * 512 + col];
        s += v; s2 += v * v;
    }
    __shared__ float sh[8][32];
    __shared__ float sh2[8][32];
    sh[threadIdx.y][threadIdx.x]  = s;
    sh2[threadIdx.y][threadIdx.x] = s2;
    __syncthreads();
    if (threadIdx.y == 0) {
        for (int y = 1; y < 8; y++) { s += sh[y][threadIdx.x]; s2 += sh2[y][threadIdx.x]; }
        float m   = s * (1.f / 4096.f);
        float var = s2 * (1.f / 4096.f) - m * m;   // biased var (ddof=0)
        mean[col] = m;
        rstd[col] = rsqrtf(var + 1e-5f);
    }
}

__global__ void bn_apply_kernel(float* __restrict__ h,
                                const float* __restrict__ mean, const float* __restrict__ rstd,
                                const float* __restrict__ g, const float* __restrict__ b)
{
    const int i = blockIdx.x * 256 + threadIdx.x;
    if (i < 4096 * 512) {
        const int c = i & 511;
        float v = (h[i] - mean[c]) * rstd[c] * g[c] + b[c];
        h[i] = fmaxf(v, 0.f);
    }
}

// ---------------------------------------------------------------------------
// 50-iteration continuous top-k, one block per row, row resident in registers.
// MUFU work gated behind warp votes: only elements with w >= max-3.0 matter
// (onehot < e^-30 below that; fp32 reference produces exactly-zero updates
// there too, so skipping is numerically identical at our tolerance).
// Also fuses the Gumbel perturbation on load and xm = x*subset on store.
// ---------------------------------------------------------------------------
__global__ __launch_bounds__(512)
void topk_kernel(const float* __restrict__ w_in, const float* __restrict__ noise,
                 const float* __restrict__ x, float* __restrict__ xm)
{
    const int row = blockIdx.x;
    const int t = threadIdx.x;
    const size_t base = (size_t)row * 5000;
    const int lane = t & 31, wid = t >> 5;

    float wv[10], kh[10], e[10];
#pragma unroll
    for (int i = 0; i < 10; i++) {
        const int j = t + i * 512;
        kh[i] = 0.f;
        if (j < 5000) {
            // fp32 of (1-1e-30)*u + 1e-30 is exactly u + 1e-30f
            float u = noise[base + j] + 1e-30f;
            wv[i] = w_in[base + j] + __logf(-__logf(u));
        } else {
            wv[i] = -3.0e38f;
        }
    }

    __shared__ float red[16];
    __shared__ float bc;

    for (int it = 0; it < 50; it++) {
        // ---- row max ----
        float m = wv[0];
#pragma unroll
        for (int i = 1; i < 10; i++) m = fmaxf(m, wv[i]);
#pragma unroll
        for (int o = 16; o > 0; o >>= 1) m = fmaxf(m, __shfl_xor_sync(0xffffffffu, m, o));
        if (lane == 0) red[wid] = m;
        __syncthreads();
        if (t == 0) {
            float mm = red[0];
            for (int k = 1; k < 16; k++) mm = fmaxf(mm, red[k]);
            bc = mm;
        }
        __syncthreads();
        m = bc;
        const float thresh = m - 3.0f;   // exp((w-m)/T) < e^-30 below this

        // ---- exp + row sum (warp-vote gated) ----
        float s = 0.f;
#pragma unroll
        for (int i = 0; i < 10; i++) {
            e[i] = 0.f;
            if (__any_sync(0xffffffffu, wv[i] >= thresh)) {
                if (wv[i] >= thresh) {
                    float ee = __expf((wv[i] - m) * 10.0f);
                    e[i] = ee;
                    s += ee;
                }
            }
        }
#pragma unroll
        for (int o = 16; o > 0; o >>= 1) s += __shfl_xor_sync(0xffffffffu, s, o);
        if (lane == 0) red[wid] = s;
        __syncthreads();
        if (t == 0) {
            float ss = red[0];
            for (int k = 1; k < 16; k++) ss += red[k];
            bc = ss;
        }
        __syncthreads();
        const float inv = 1.0f / bc;   // sum >= exp(0) = 1

        // ---- khot accumulate + w suppression (gated) ----
#pragma unroll
        for (int i = 0; i < 10; i++) {
            if (__any_sync(0xffffffffu, e[i] > 0.f)) {
                if (e[i] > 0.f) {
                    float oh = e[i] * inv;
                    kh[i] += oh;
                    float mk = fmaxf(1.0f - oh, 1e-30f);
                    if (mk < 1.0f) wv[i] += __logf(mk);
                }
            }
        }
    }

#pragma unroll
    for (int i = 0; i < 10; i++) {
        const int j = t + i * 512;
        if (j < 5000) xm[base + j] = x[base + j] * kh[i];
    }
}

// ---------------------------------------------------------------------------
// z = mu + eps * exp(0.5 * logvar)
// ---------------------------------------------------------------------------
__global__ void reparam_kernel(const float* __restrict__ mu, const float* __restrict__ lv,
                               const float* __restrict__ eps, float* __restrict__ z)
{
    const int i = blockIdx.x * 256 + threadIdx.x;
    if (i < 4096 * 64) z[i] = fmaf(eps[i], __expf(0.5f * lv[i]), mu[i]);
}

// ---------------------------------------------------------------------------
extern "C" void kernel_launch(void* const* d_in, const int* in_sizes, int n_in,
                              void* d_out, int out_size)
{
    const float* x     = (const float*)d_in[0];
    const float* noise = (const float*)d_in[1];
    const float* eps   = (const float*)d_in[2];
    const float* wc_w1 = (const float*)d_in[3];
    const float* wc_b1 = (const float*)d_in[4];
    const float* bn_g  = (const float*)d_in[5];
    const float* bn_b  = (const float*)d_in[6];
    const float* wc_w2 = (const float*)d_in[7];
    const float* wc_b2 = (const float*)d_in[8];
    const float* e_w1  = (const float*)d_in[9];
    const float* e_b1  = (const float*)d_in[10];
    const float* e_w2  = (const float*)d_in[11];
    const float* e_b2  = (const float*)d_in[12];
    const float* e_w3  = (const float*)d_in[13];
    const float* e_b3  = (const float*)d_in[14];
    const float* e_w4  = (const float*)d_in[15];
    const float* e_b4  = (const float*)d_in[16];
    const float* m_w   = (const float*)d_in[17];
    const float* m_b   = (const float*)d_in[18];
    const float* lvw   = (const float*)d_in[19];
    const float* lvb   = (const float*)d_in[20];
    const float* d_w1  = (const float*)d_in[21];
    const float* d_b1  = (const float*)d_in[22];
    const float* d_w2  = (const float*)d_in[23];
    const float* d_b2  = (const float*)d_in[24];

    float* out     = (float*)d_out;
    float* out_mux = out;                               // [4096,5000]
    float* out_mu  = out + (size_t)4096 * 5000;         // [4096,64]
    float* out_lv  = out_mu + (size_t)4096 * 64;        // [4096,64]

    float *h, *w, *xm, *h1, *h2, *h3, *z, *dh, *mean, *rstd;
    cudaGetSymbolAddress((void**)&h,    g_h);
    cudaGetSymbolAddress((void**)&w,    g_w);
    cudaGetSymbolAddress((void**)&xm,   g_xm);
    cudaGetSymbolAddress((void**)&h1,   g_h1);
    cudaGetSymbolAddress((void**)&h2,   g_h2);
    cudaGetSymbolAddress((void**)&h3,   g_h3);
    cudaGetSymbolAddress((void**)&z,    g_z);
    cudaGetSymbolAddress((void**)&dh,   g_dh);
    cudaGetSymbolAddress((void**)&mean, g_mean);
    cudaGetSymbolAddress((void**)&rstd, g_rstd);

    const dim3 blk(256);
    auto grd = [](int M, int N) { return dim3((N + BN - 1) / BN, (M + BM - 1) / BM); };

    // weight_creator
    sgemm_kernel<EPI_NONE><<<grd(4096, 512), blk>>>(x, wc_w1, wc_b1, h, 4096, 512, 5000);
    bn_stats_kernel<<<16, dim3(32, 8)>>>(h, mean, rstd);
    bn_apply_kernel<<<(4096 * 512 + 255) / 256, 256>>>(h, mean, rstd, bn_g, bn_b);
    sgemm_kernel<EPI_NONE><<<grd(4096, 5000), blk>>>(h, wc_w2, wc_b2, w, 4096, 5000, 512);

    // gumbel + 50-step continuous top-k + mask
    topk_kernel<<<4096, 512>>>(w, noise, x, xm);

    // encoder
    sgemm_kernel<EPI_LEAKY><<<grd(4096, 1024), blk>>>(xm, e_w1, e_b1, h1, 4096, 1024, 5000);
    sgemm_kernel<EPI_LEAKY><<<grd(4096, 512),  blk>>>(h1, e_w2, e_b2, h2, 4096, 512, 1024);
    sgemm_kernel<EPI_LEAKY><<<grd(4096, 512),  blk>>>(h2, e_w3, e_b3, h3, 4096, 512, 512);
    sgemm_kernel<EPI_LEAKY><<<grd(4096, 512),  blk>>>(h3, e_w4, e_b4, h2, 4096, 512, 512);
    sgemm_kernel<EPI_NONE><<<grd(4096, 64),    blk>>>(h2, m_w,  m_b,  out_mu, 4096, 64, 512);
    sgemm_kernel<EPI_NONE><<<grd(4096, 64),    blk>>>(h2, lvw,  lvb,  out_lv, 4096, 64, 512);

    // reparameterize + decoder
    reparam_kernel<<<(4096 * 64 + 255) / 256, 256>>>(out_mu, out_lv, eps, z);
    sgemm_kernel<EPI_LEAKY><<<grd(4096, 1024),   blk>>>(z,  d_w1, d_b1, dh, 4096, 1024, 64);
    sgemm_kernel<EPI_SIGMOID><<<grd(4096, 5000), blk>>>(dh, d_w2, d_b2, out_mux, 4096, 5000, 1024);
}

// round 3
// speedup vs baseline: 1.0720x; 1.0720x over previous
#include <cuda_runtime.h>
#include <math.h>

// ---------------------------------------------------------------------------
// VAE_Gumbel: B=4096, D=5000, H=512, Z=64, K=50, T=0.1
// R3: fix sparse-topk truncation (threshold kh>1e-5, cap 2048).
//     f32x2 packed-FMA SGEMM + double buffering retained from R2.
// ---------------------------------------------------------------------------

#define BN 128
#define BK 8
#define TN 8
#define SPCAP 2048

enum { EPI_NONE = 0, EPI_LEAKY = 2, EPI_SIGMOID = 3 };

// Scratch (static device globals; no runtime allocation allowed)
__device__ float g_h  [4096u * 512];
__device__ float g_w  [4096u * 5000];
__device__ float g_h1 [4096u * 1024];
__device__ float g_h2 [4096u * 512];
__device__ float g_h3 [4096u * 512];
__device__ float g_z  [4096u * 64];
__device__ float g_dh [4096u * 1024];
__device__ float g_mean[512];
__device__ float g_rstd[512];
__device__ float g_spv[4096u * SPCAP];
__device__ int   g_spi[4096u * SPCAP];
__device__ int   g_spc[4096];

// ---- f32x2 packed helpers --------------------------------------------------
__device__ __forceinline__ unsigned long long pack2(float x, float y) {
    unsigned long long r;
    asm("mov.b64 %0, {%1, %2};" : "=l"(r) : "f"(x), "f"(y));
    return r;
}
__device__ __forceinline__ void unpack2(unsigned long long v, float& x, float& y) {
    asm("mov.b64 {%0, %1}, %2;" : "=f"(x), "=f"(y) : "l"(v));
}
__device__ __forceinline__ void ffma2(unsigned long long& d,
                                      unsigned long long a, unsigned long long b) {
    asm("fma.rn.f32x2 %0, %1, %2, %0;" : "+l"(d) : "l"(a), "l"(b));
}

// ---------------------------------------------------------------------------
// Register-tiled fp32 SGEMM with f32x2 FMA + double-buffered smem.
// A[M,K], B[K,N] row-major, C = act(A@B + bias).
// BN=128, BK=8 fixed; BMT in {128,64}, TMT = BMT/16, TN=8.
// Requires K%8==0, N%4==0, M%BMT==0.
// ---------------------------------------------------------------------------
template <int EPI, int BMT, int TMT>
__global__ __launch_bounds__(256, 2)
void sgemm_kernel(const float* __restrict__ A, const float* __restrict__ B,
                  const float* __restrict__ bias, float* __restrict__ C,
                  int M, int N, int K)
{
    __shared__ float As[2][BK][BMT];
    __shared__ float Bs[2][BK][BN];

    const int tid  = threadIdx.x;
    const int row0 = blockIdx.y * BMT;
    const int col0 = blockIdx.x * BN;

    const bool aload = tid < 2 * BMT;
    const int aRow = tid >> 1;
    const int aCol = (tid & 1) << 2;
    const int bRow = tid >> 5;
    const int bCol = (tid & 31) << 2;

    const int tx = tid & 15;
    const int ty = tid >> 4;
    const int mBase = ty * TMT;
    const int nBase = tx * TN;

    unsigned long long acc2[TMT / 2][TN];
#pragma unroll
    for (int i = 0; i < TMT / 2; i++)
#pragma unroll
        for (int j = 0; j < TN; j++) acc2[i][j] = 0ull;

    const float* Abase = A + (size_t)(row0 + aRow) * K + aCol;
    const float* Bbase = B + (size_t)bRow * N + col0 + bCol;
    const bool bvalid = (col0 + bCol) < N;

    {
        float4 a4 = make_float4(0.f, 0.f, 0.f, 0.f);
        float4 b4 = make_float4(0.f, 0.f, 0.f, 0.f);
        if (aload)  a4 = *(const float4*)(Abase);
        if (bvalid) b4 = *(const float4*)(Bbase);
        if (aload) {
            As[0][aCol + 0][aRow] = a4.x;
            As[0][aCol + 1][aRow] = a4.y;
            As[0][aCol + 2][aRow] = a4.z;
            As[0][aCol + 3][aRow] = a4.w;
        }
        *(float4*)&Bs[0][bRow][bCol] = b4;
    }
    __syncthreads();

    int buf = 0;
    for (int kt = 0; kt < K; kt += BK) {
        const bool nxt = (kt + BK) < K;
        float4 a4n = make_float4(0.f, 0.f, 0.f, 0.f);
        float4 b4n = make_float4(0.f, 0.f, 0.f, 0.f);
        if (nxt) {
            if (aload)  a4n = *(const float4*)(Abase + kt + BK);
            if (bvalid) b4n = *(const float4*)(Bbase + (size_t)(kt + BK) * N);
        }

#pragma unroll
        for (int kk = 0; kk < BK; kk++) {
            unsigned long long a2[TMT / 2];
#pragma unroll
            for (int i2 = 0; i2 < TMT / 2; i2++)
                a2[i2] = *(const unsigned long long*)&As[buf][kk][mBase + 2 * i2];
            float bv[TN];
            *(float4*)&bv[0] = *(const float4*)&Bs[buf][kk][nBase];
            *(float4*)&bv[4] = *(const float4*)&Bs[buf][kk][nBase + 4];
            unsigned long long b2[TN];
#pragma unroll
            for (int j = 0; j < TN; j++) b2[j] = pack2(bv[j], bv[j]);
#pragma unroll
            for (int i2 = 0; i2 < TMT / 2; i2++)
#pragma unroll
                for (int j = 0; j < TN; j++)
                    ffma2(acc2[i2][j], a2[i2], b2[j]);
        }

        if (nxt) {
            if (aload) {
                As[buf ^ 1][aCol + 0][aRow] = a4n.x;
                As[buf ^ 1][aCol + 1][aRow] = a4n.y;
                As[buf ^ 1][aCol + 2][aRow] = a4n.z;
                As[buf ^ 1][aCol + 3][aRow] = a4n.w;
            }
            *(float4*)&Bs[buf ^ 1][bRow][bCol] = b4n;
            __syncthreads();
            buf ^= 1;
        }
    }

#pragma unroll
    for (int i2 = 0; i2 < TMT / 2; i2++) {
        const int r = row0 + mBase + 2 * i2;
#pragma unroll
        for (int j = 0; j < TN; j++) {
            const int c = col0 + nBase + j;
            if (c < N) {
                float lo, hi;
                unpack2(acc2[i2][j], lo, hi);
                const float bc = bias[c];
                float v0 = lo + bc, v1 = hi + bc;
                if (EPI == EPI_LEAKY) {
                    v0 = v0 > 0.f ? v0 : 0.01f * v0;
                    v1 = v1 > 0.f ? v1 : 0.01f * v1;
                }
                if (EPI == EPI_SIGMOID) {
                    v0 = 1.0f / (1.0f + __expf(-v0));
                    v1 = 1.0f / (1.0f + __expf(-v1));
                }
                C[(size_t)r * N + c]       = v0;
                C[(size_t)(r + 1) * N + c] = v1;
            }
        }
    }
}

// ---------------------------------------------------------------------------
__global__ void bn_stats_kernel(const float* __restrict__ h,
                                float* __restrict__ mean, float* __restrict__ rstd)
{
    const int col = blockIdx.x * 32 + threadIdx.x;
    float s = 0.f, s2 = 0.f;
    for (int r = threadIdx.y; r < 4096; r += 8) {
        float v = h[(size_t)r * 512 + col];
        s += v; s2 += v * v;
    }
    __shared__ float sh[8][32];
    __shared__ float sh2[8][32];
    sh[threadIdx.y][threadIdx.x]  = s;
    sh2[threadIdx.y][threadIdx.x] = s2;
    __syncthreads();
    if (threadIdx.y == 0) {
        for (int y = 1; y < 8; y++) { s += sh[y][threadIdx.x]; s2 += sh2[y][threadIdx.x]; }
        float m   = s * (1.f / 4096.f);
        float var = s2 * (1.f / 4096.f) - m * m;
        mean[col] = m;
        rstd[col] = rsqrtf(var + 1e-5f);
    }
}

__global__ void bn_apply_kernel(float* __restrict__ h,
                                const float* __restrict__ mean, const float* __restrict__ rstd,
                                const float* __restrict__ g, const float* __restrict__ b)
{
    const int i = blockIdx.x * 256 + threadIdx.x;
    if (i < 4096 * 512) {
        const int c = i & 511;
        float v = (h[i] - mean[c]) * rstd[c] * g[c] + b[c];
        h[i] = fmaxf(v, 0.f);
    }
}

// ---------------------------------------------------------------------------
// 50-iteration continuous top-k; emits compact (idx, x*kh) for kh > 1e-5.
// Dropped mass <= 1e-2 of sum(kh)=50 -> rel impact ~4e-5 on h1 (<< 1e-3).
// ---------------------------------------------------------------------------
__global__ __launch_bounds__(512)
void topk_kernel(const float* __restrict__ w_in, const float* __restrict__ noise,
                 const float* __restrict__ x,
                 float* __restrict__ spv, int* __restrict__ spi, int* __restrict__ spc)
{
    const int row = blockIdx.x;
    const int t = threadIdx.x;
    const size_t base = (size_t)row * 5000;
    const int lane = t & 31, wid = t >> 5;

    float wv[10], kh[10], e[10];
#pragma unroll
    for (int i = 0; i < 10; i++) {
        const int j = t + i * 512;
        kh[i] = 0.f;
        if (j < 5000) {
            float u = noise[base + j] + 1e-30f;   // fp32((1-eps)*u + eps) == u + 1e-30f
            wv[i] = w_in[base + j] + __logf(-__logf(u));
        } else {
            wv[i] = -3.0e38f;
        }
    }

    __shared__ float red[16];
    __shared__ float bc;
    __shared__ int s_cnt;
    if (t == 0) s_cnt = 0;

    for (int it = 0; it < 50; it++) {
        float m = wv[0];
#pragma unroll
        for (int i = 1; i < 10; i++) m = fmaxf(m, wv[i]);
#pragma unroll
        for (int o = 16; o > 0; o >>= 1) m = fmaxf(m, __shfl_xor_sync(0xffffffffu, m, o));
        if (lane == 0) red[wid] = m;
        __syncthreads();
        if (t == 0) {
            float mm = red[0];
            for (int k = 1; k < 16; k++) mm = fmaxf(mm, red[k]);
            bc = mm;
        }
        __syncthreads();
        m = bc;
        const float thresh = m - 3.0f;

        float s = 0.f;
#pragma unroll
        for (int i = 0; i < 10; i++) {
            e[i] = 0.f;
            if (__any_sync(0xffffffffu, wv[i] >= thresh)) {
                if (wv[i] >= thresh) {
                    float ee = __expf((wv[i] - m) * 10.0f);
                    e[i] = ee;
                    s += ee;
                }
            }
        }
#pragma unroll
        for (int o = 16; o > 0; o >>= 1) s += __shfl_xor_sync(0xffffffffu, s, o);
        if (lane == 0) red[wid] = s;
        __syncthreads();
        if (t == 0) {
            float ss = red[0];
            for (int k = 1; k < 16; k++) ss += red[k];
            bc = ss;
        }
        __syncthreads();
        const float inv = 1.0f / bc;

#pragma unroll
        for (int i = 0; i < 10; i++) {
            if (__any_sync(0xffffffffu, e[i] > 0.f)) {
                if (e[i] > 0.f) {
                    float oh = e[i] * inv;
                    kh[i] += oh;
                    float mk = fmaxf(1.0f - oh, 1e-30f);
                    if (mk < 1.0f) wv[i] += __logf(mk);
                }
            }
        }
    }

    __syncthreads();
    const size_t sb = (size_t)row * SPCAP;
#pragma unroll
    for (int i = 0; i < 10; i++) {
        const int j = t + i * 512;
        if (j < 5000 && kh[i] > 1e-5f) {
            int p = atomicAdd(&s_cnt, 1);
            if (p < SPCAP) {
                spi[sb + p] = j;
                spv[sb + p] = x[base + j] * kh[i];
            }
        }
    }
    __syncthreads();
    if (t == 0) spc[row] = min(s_cnt, SPCAP);
}

// ---------------------------------------------------------------------------
// Sparse h1 = leaky(xm @ enc_w1 + b). One block per row; thread t owns
// cols [4t, 4t+4). W rows gathered from L2 (enc_w1 = 20MB, L2-resident).
// ---------------------------------------------------------------------------
__global__ __launch_bounds__(256)
void spmm_kernel(const float* __restrict__ spv, const int* __restrict__ spi,
                 const int* __restrict__ spc,
                 const float* __restrict__ W, const float* __restrict__ bias,
                 float* __restrict__ out)
{
    const int row = blockIdx.x;
    const int t = threadIdx.x;
    const int cnt = spc[row];
    const int col = t * 4;
    const size_t sb = (size_t)row * SPCAP;

    float ax = 0.f, ay = 0.f, az = 0.f, aw = 0.f;
    __shared__ float sv[256];
    __shared__ int   si[256];

    for (int s0 = 0; s0 < cnt; s0 += 256) {
        const int n = min(256, cnt - s0);
        if (t < n) { sv[t] = spv[sb + s0 + t]; si[t] = spi[sb + s0 + t]; }
        __syncthreads();
        int s = 0;
        for (; s + 4 <= n; s += 4) {
            float4 w0 = *(const float4*)&W[(size_t)si[s + 0] * 1024 + col];
            float4 w1 = *(const float4*)&W[(size_t)si[s + 1] * 1024 + col];
            float4 w2 = *(const float4*)&W[(size_t)si[s + 2] * 1024 + col];
            float4 w3 = *(const float4*)&W[(size_t)si[s + 3] * 1024 + col];
            float v0 = sv[s + 0], v1 = sv[s + 1], v2 = sv[s + 2], v3 = sv[s + 3];
            ax = fmaf(v0, w0.x, ax); ay = fmaf(v0, w0.y, ay); az = fmaf(v0, w0.z, az); aw = fmaf(v0, w0.w, aw);
            ax = fmaf(v1, w1.x, ax); ay = fmaf(v1, w1.y, ay); az = fmaf(v1, w1.z, az); aw = fmaf(v1, w1.w, aw);
            ax = fmaf(v2, w2.x, ax); ay = fmaf(v2, w2.y, ay); az = fmaf(v2, w2.z, az); aw = fmaf(v2, w2.w, aw);
            ax = fmaf(v3, w3.x, ax); ay = fmaf(v3, w3.y, ay); az = fmaf(v3, w3.z, az); aw = fmaf(v3, w3.w, aw);
        }
        for (; s < n; s++) {
            float4 w0 = *(const float4*)&W[(size_t)si[s] * 1024 + col];
            float v0 = sv[s];
            ax = fmaf(v0, w0.x, ax); ay = fmaf(v0, w0.y, ay); az = fmaf(v0, w0.z, az); aw = fmaf(v0, w0.w, aw);
        }
        __syncthreads();
    }

    float4 b4 = *(const float4*)&bias[col];
    float4 o;
    o.x = ax + b4.x; o.y = ay + b4.y; o.z = az + b4.z; o.w = aw + b4.w;
    o.x = o.x > 0.f ? o.x : 0.01f * o.x;
    o.y = o.y > 0.f ? o.y : 0.01f * o.y;
    o.z = o.z > 0.f ? o.z : 0.01f * o.z;
    o.w = o.w > 0.f ? o.w : 0.01f * o.w;
    *(float4*)&out[(size_t)row * 1024 + col] = o;
}

// ---------------------------------------------------------------------------
__global__ void reparam_kernel(const float* __restrict__ mu, const float* __restrict__ lv,
                               const float* __restrict__ eps, float* __restrict__ z)
{
    const int i = blockIdx.x * 256 + threadIdx.x;
    if (i < 4096 * 64) z[i] = fmaf(eps[i], __expf(0.5f * lv[i]), mu[i]);
}

// ---------------------------------------------------------------------------
extern "C" void kernel_launch(void* const* d_in, const int* in_sizes, int n_in,
                              void* d_out, int out_size)
{
    const float* x     = (const float*)d_in[0];
    const float* noise = (const float*)d_in[1];
    const float* eps   = (const float*)d_in[2];
    const float* wc_w1 = (const float*)d_in[3];
    const float* wc_b1 = (const float*)d_in[4];
    const float* bn_g  = (const float*)d_in[5];
    const float* bn_b  = (const float*)d_in[6];
    const float* wc_w2 = (const float*)d_in[7];
    const float* wc_b2 = (const float*)d_in[8];
    const float* e_w1  = (const float*)d_in[9];
    const float* e_b1  = (const float*)d_in[10];
    const float* e_w2  = (const float*)d_in[11];
    const float* e_b2  = (const float*)d_in[12];
    const float* e_w3  = (const float*)d_in[13];
    const float* e_b3  = (const float*)d_in[14];
    const float* e_w4  = (const float*)d_in[15];
    const float* e_b4  = (const float*)d_in[16];
    const float* m_w   = (const float*)d_in[17];
    const float* m_b   = (const float*)d_in[18];
    const float* lvw   = (const float*)d_in[19];
    const float* lvb   = (const float*)d_in[20];
    const float* d_w1  = (const float*)d_in[21];
    const float* d_b1  = (const float*)d_in[22];
    const float* d_w2  = (const float*)d_in[23];
    const float* d_b2  = (const float*)d_in[24];

    float* out     = (float*)d_out;
    float* out_mux = out;
    float* out_mu  = out + (size_t)4096 * 5000;
    float* out_lv  = out_mu + (size_t)4096 * 64;

    float *h, *w, *h1, *h2, *h3, *z, *dh, *mean, *rstd, *spv;
    int *spi, *spc;
    cudaGetSymbolAddress((void**)&h,    g_h);
    cudaGetSymbolAddress((void**)&w,    g_w);
    cudaGetSymbolAddress((void**)&h1,   g_h1);
    cudaGetSymbolAddress((void**)&h2,   g_h2);
    cudaGetSymbolAddress((void**)&h3,   g_h3);
    cudaGetSymbolAddress((void**)&z,    g_z);
    cudaGetSymbolAddress((void**)&dh,   g_dh);
    cudaGetSymbolAddress((void**)&mean, g_mean);
    cudaGetSymbolAddress((void**)&rstd, g_rstd);
    cudaGetSymbolAddress((void**)&spv,  g_spv);
    cudaGetSymbolAddress((void**)&spi,  g_spi);
    cudaGetSymbolAddress((void**)&spc,  g_spc);

    const dim3 blk(256);
    auto grd = [](int M, int N, int bm) { return dim3((N + BN - 1) / BN, M / bm); };

    // weight_creator
    sgemm_kernel<EPI_NONE, 64, 4><<<grd(4096, 512, 64), blk>>>(x, wc_w1, wc_b1, h, 4096, 512, 5000);
    bn_stats_kernel<<<16, dim3(32, 8)>>>(h, mean, rstd);
    bn_apply_kernel<<<(4096 * 512 + 255) / 256, 256>>>(h, mean, rstd, bn_g, bn_b);
    sgemm_kernel<EPI_NONE, 128, 8><<<grd(4096, 5000, 128), blk>>>(h, wc_w2, wc_b2, w, 4096, 5000, 512);

    // gumbel + 50-step continuous top-k -> compact sparse xm
    topk_kernel<<<4096, 512>>>(w, noise, x, spv, spi, spc);

    // encoder (layer 1 sparse)
    spmm_kernel<<<4096, 256>>>(spv, spi, spc, e_w1, e_b1, h1);
    sgemm_kernel<EPI_LEAKY, 64, 4><<<grd(4096, 512, 64), blk>>>(h1, e_w2, e_b2, h2, 4096, 512, 1024);
    sgemm_kernel<EPI_LEAKY, 64, 4><<<grd(4096, 512, 64), blk>>>(h2, e_w3, e_b3, h3, 4096, 512, 512);
    sgemm_kernel<EPI_LEAKY, 64, 4><<<grd(4096, 512, 64), blk>>>(h3, e_w4, e_b4, h2, 4096, 512, 512);
    sgemm_kernel<EPI_NONE, 64, 4><<<grd(4096, 64, 64), blk>>>(h2, m_w, m_b, out_mu, 4096, 64, 512);
    sgemm_kernel<EPI_NONE, 64, 4><<<grd(4096, 64, 64), blk>>>(h2, lvw, lvb, out_lv, 4096, 64, 512);

    // reparameterize + decoder
    reparam_kernel<<<(4096 * 64 + 255) / 256, 256>>>(out_mu, out_lv, eps, z);
    sgemm_kernel<EPI_LEAKY, 128, 8><<<grd(4096, 1024, 128), blk>>>(z, d_w1, d_b1, dh, 4096, 1024, 64);
    sgemm_kernel<EPI_SIGMOID, 128, 8><<<grd(4096, 5000, 128), blk>>>(dh, d_w2, d_b2, out_mux, 4096, 5000, 1024);
}

// round 8
// speedup vs baseline: 1.5817x; 1.4755x over previous
#include <cuda_runtime.h>
#include <cuda_bf16.h>

typedef unsigned int u32;
typedef unsigned long long u64;

// ---------------------------------------------------------------------------
// VAE_Gumbel R8: harness targets compute_103 (non-'a') -> tcgen05 unavailable.
// Use arch-portable ldmatrix + mma.sync.m16n8k16 bf16x3 split GEMM instead.
// B=4096, D=5000, H=512, Z=64.
// ---------------------------------------------------------------------------

#define SPCAP 2048
enum { EPI_NONE = 0, EPI_LEAKY = 2, EPI_SIGMOID = 3 };

#define AST 72    // A smem row stride (bf16 elems), 144B = 9*16B -> conflict-free ldmatrix
#define BST 136   // B smem row stride (bf16 elems), 272B = 17*16B -> conflict-free

__device__ __forceinline__ u32 smem_u32(const void* p) {
    u32 a;
    asm("{ .reg .u64 t; cvta.to.shared.u64 t, %1; cvt.u32.u64 %0, t; }"
        : "=r"(a) : "l"(p));
    return a;
}

__device__ __forceinline__ void ldsm_x4(u32& r0, u32& r1, u32& r2, u32& r3, u32 addr) {
    asm volatile("ldmatrix.sync.aligned.m8n8.x4.shared.b16 {%0,%1,%2,%3}, [%4];"
                 : "=r"(r0), "=r"(r1), "=r"(r2), "=r"(r3) : "r"(addr));
}
__device__ __forceinline__ void ldsm_x2t(u32& r0, u32& r1, u32 addr) {
    asm volatile("ldmatrix.sync.aligned.m8n8.x2.trans.shared.b16 {%0,%1}, [%2];"
                 : "=r"(r0), "=r"(r1) : "r"(addr));
}
__device__ __forceinline__ void mma_bf16(float* d, const u32* a, const u32* b) {
    asm volatile("mma.sync.aligned.m16n8k16.row.col.f32.bf16.bf16.f32 "
                 "{%0,%1,%2,%3}, {%4,%5,%6,%7}, {%8,%9}, {%0,%1,%2,%3};"
                 : "+f"(d[0]), "+f"(d[1]), "+f"(d[2]), "+f"(d[3])
                 : "r"(a[0]), "r"(a[1]), "r"(a[2]), "r"(a[3]), "r"(b[0]), "r"(b[1]));
}

__device__ __forceinline__ u64 pack4bf(float v0, float v1, float v2, float v3,
                                       u64& lo_out) {
    __nv_bfloat16 h0 = __float2bfloat16(v0);
    __nv_bfloat16 h1 = __float2bfloat16(v1);
    __nv_bfloat16 h2 = __float2bfloat16(v2);
    __nv_bfloat16 h3 = __float2bfloat16(v3);
    __nv_bfloat16 l0 = __float2bfloat16(v0 - __bfloat162float(h0));
    __nv_bfloat16 l1 = __float2bfloat16(v1 - __bfloat162float(h1));
    __nv_bfloat16 l2 = __float2bfloat16(v2 - __bfloat162float(h2));
    __nv_bfloat16 l3 = __float2bfloat16(v3 - __bfloat162float(h3));
    lo_out = (u64)*(unsigned short*)&l0 | ((u64)*(unsigned short*)&l1 << 16)
           | ((u64)*(unsigned short*)&l2 << 32) | ((u64)*(unsigned short*)&l3 << 48);
    return (u64)*(unsigned short*)&h0 | ((u64)*(unsigned short*)&h1 << 16)
         | ((u64)*(unsigned short*)&h2 << 32) | ((u64)*(unsigned short*)&h3 << 48);
}

// ---------------------------------------------------------------------------
// bf16x3 split tensor-core GEMM: C[M,N] = act(A[M,K] @ B[K,N] + bias)
// Tile 128x128, K chunk 64, 8 warps (4x2), warp tile 32x64.
// Requires M%128==0, K%4==0, N%4==0 (true for all layers here).
// ---------------------------------------------------------------------------
template <int EPI>
__global__ __launch_bounds__(256)
void mma_gemm(const float* __restrict__ A, const float* __restrict__ B,
              const float* __restrict__ bias, float* __restrict__ C,
              int M, int N, int K)
{
    extern __shared__ __nv_bfloat16 smem[];
    __nv_bfloat16* Ash_h = smem;                       // [128][AST]
    __nv_bfloat16* Ash_l = Ash_h + 128 * AST;
    __nv_bfloat16* Bsh_h = Ash_l + 128 * AST;          // [64][BST]
    __nv_bfloat16* Bsh_l = Bsh_h + 64 * BST;

    const int tid = threadIdx.x, lane = tid & 31, wid = tid >> 5;
    const int wm = (wid & 3) * 32;     // warp row offset within 128 tile
    const int wn = (wid >> 2) * 64;    // warp col offset within 128 tile
    const int row0 = blockIdx.y * 128, n0 = blockIdx.x * 128;

    const u32 aBase = smem_u32(Ash_h);
    const u32 alBase = smem_u32(Ash_l);
    const u32 bBase = smem_u32(Bsh_h);
    const u32 blBase = smem_u32(Bsh_l);

    float acc[2][8][4];
#pragma unroll
    for (int i = 0; i < 2; i++)
#pragma unroll
        for (int j = 0; j < 8; j++)
#pragma unroll
            for (int q = 0; q < 4; q++) acc[i][j][q] = 0.f;

    // gmem->smem mapping
    const int ar = tid >> 1;               // A row 0..127
    const int ak = (tid & 1) * 4;          // + j*8 -> k offsets {0,4}+8j
    const int bk = tid >> 2;               // B k-row 0..63
    const int bn = (tid & 3) * 4;          // + j*16 -> n offsets

    // ldmatrix address components (within-tile)
    const int lm15 = lane & 15;
    const int lm16 = (lane >> 4) * 8;

    const int nchunks = (K + 63) / 64;
    for (int ch = 0; ch < nchunks; ch++) {
        const int k0 = ch * 64;
        __syncthreads();   // protect previous iteration's frags

        // ---- stage A [128 x 64] hi/lo ----
        {
            const float* Ap = A + (size_t)(row0 + ar) * K + k0 + ak;
#pragma unroll
            for (int j = 0; j < 8; j++) {
                const int koff = ak + 8 * j;
                float4 v = (k0 + koff < K) ? *(const float4*)(Ap + 8 * j)
                                           : make_float4(0.f, 0.f, 0.f, 0.f);
                u64 lo;
                u64 hi = pack4bf(v.x, v.y, v.z, v.w, lo);
                const int off = ar * AST + koff;
                *(u64*)(Ash_h + off) = hi;
                *(u64*)(Ash_l + off) = lo;
            }
        }
        // ---- stage B [64 x 128] hi/lo ----
        {
            const float* Bp = B + (size_t)(k0 + bk) * N + n0 + bn;
            const bool kval = (k0 + bk) < K;
#pragma unroll
            for (int j = 0; j < 8; j++) {
                const int noff = bn + 16 * j;
                float4 v = (kval && (n0 + noff) < N) ? *(const float4*)(Bp + 16 * j)
                                                     : make_float4(0.f, 0.f, 0.f, 0.f);
                u64 lo;
                u64 hi = pack4bf(v.x, v.y, v.z, v.w, lo);
                const int off = bk * BST + noff;
                *(u64*)(Bsh_h + off) = hi;
                *(u64*)(Bsh_l + off) = lo;
            }
        }
        __syncthreads();

        // ---- 4 x k16 MMA steps ----
#pragma unroll
        for (int ks = 0; ks < 4; ks++) {
            u32 afh[2][4], afl[2][4];
#pragma unroll
            for (int mi = 0; mi < 2; mi++) {
                const u32 aoff = (u32)((wm + mi * 16 + lm15) * AST + ks * 16 + lm16) * 2;
                ldsm_x4(afh[mi][0], afh[mi][1], afh[mi][2], afh[mi][3], aBase + aoff);
                ldsm_x4(afl[mi][0], afl[mi][1], afl[mi][2], afl[mi][3], alBase + aoff);
            }
            u32 bfh[8][2], bfl[8][2];
#pragma unroll
            for (int ni = 0; ni < 8; ni++) {
                const u32 boff = (u32)((ks * 16 + lm15) * BST + wn + ni * 8) * 2;
                ldsm_x2t(bfh[ni][0], bfh[ni][1], bBase + boff);
                ldsm_x2t(bfl[ni][0], bfl[ni][1], blBase + boff);
            }
#pragma unroll
            for (int mi = 0; mi < 2; mi++)
#pragma unroll
                for (int ni = 0; ni < 8; ni++) {
                    mma_bf16(acc[mi][ni], afh[mi], bfh[ni]);
                    mma_bf16(acc[mi][ni], afh[mi], bfl[ni]);
                    mma_bf16(acc[mi][ni], afl[mi], bfh[ni]);
                }
        }
    }

    // ---- epilogue: standard m16n8 accum layout -> gmem ----
    const int rg = lane >> 2;          // row in group (0..7)
    const int cp = (lane & 3) * 2;     // col pair base
#pragma unroll
    for (int mi = 0; mi < 2; mi++) {
#pragma unroll
        for (int ni = 0; ni < 8; ni++) {
            const int c = n0 + wn + ni * 8 + cp;
            if (c < N) {   // N even and c even -> c+1 < N too
                const float b0 = bias[c], b1 = bias[c + 1];
#pragma unroll
                for (int half = 0; half < 2; half++) {
                    const int r = row0 + wm + mi * 16 + rg + half * 8;
                    float v0 = acc[mi][ni][2 * half]     + b0;
                    float v1 = acc[mi][ni][2 * half + 1] + b1;
                    if (EPI == EPI_LEAKY) {
                        v0 = v0 > 0.f ? v0 : 0.01f * v0;
                        v1 = v1 > 0.f ? v1 : 0.01f * v1;
                    }
                    if (EPI == EPI_SIGMOID) {
                        v0 = 1.0f / (1.0f + __expf(-v0));
                        v1 = 1.0f / (1.0f + __expf(-v1));
                    }
                    C[(size_t)r * N + c]     = v0;
                    C[(size_t)r * N + c + 1] = v1;
                }
            }
        }
    }
}

#define MMA_SMEM ((2 * 128 * AST + 2 * 64 * BST) * (int)sizeof(__nv_bfloat16))

// ---------------------------------------------------------------------------
// Scratch globals
// ---------------------------------------------------------------------------
__device__ float g_h  [4096u * 512];
__device__ float g_w  [4096u * 5000];
__device__ float g_h1 [4096u * 1024];
__device__ float g_h2 [4096u * 512];
__device__ float g_h3 [4096u * 512];
__device__ float g_z  [4096u * 64];
__device__ float g_dh [4096u * 1024];
__device__ float g_mean[512];
__device__ float g_rstd[512];
__device__ float g_spv[4096u * SPCAP];
__device__ int   g_spi[4096u * SPCAP];
__device__ int   g_spc[4096];

// ---------------------------------------------------------------------------
__global__ void bn_stats_kernel(const float* __restrict__ h,
                                float* __restrict__ mean, float* __restrict__ rstd)
{
    const int col = blockIdx.x * 32 + threadIdx.x;
    float s = 0.f, s2 = 0.f;
    for (int r = threadIdx.y; r < 4096; r += 8) {
        float v = h[(size_t)r * 512 + col];
        s += v; s2 += v * v;
    }
    __shared__ float sh[8][32];
    __shared__ float sh2[8][32];
    sh[threadIdx.y][threadIdx.x]  = s;
    sh2[threadIdx.y][threadIdx.x] = s2;
    __syncthreads();
    if (threadIdx.y == 0) {
        for (int y = 1; y < 8; y++) { s += sh[y][threadIdx.x]; s2 += sh2[y][threadIdx.x]; }
        float m   = s * (1.f / 4096.f);
        float var = s2 * (1.f / 4096.f) - m * m;
        mean[col] = m;
        rstd[col] = rsqrtf(var + 1e-5f);
    }
}

__global__ void bn_apply_kernel(float* __restrict__ h,
                                const float* __restrict__ mean, const float* __restrict__ rstd,
                                const float* __restrict__ g, const float* __restrict__ b)
{
    const int i = blockIdx.x * 256 + threadIdx.x;
    if (i < 4096 * 512) {
        const int c = i & 511;
        float v = (h[i] - mean[c]) * rstd[c] * g[c] + b[c];
        h[i] = fmaxf(v, 0.f);
    }
}

// ---------------------------------------------------------------------------
// 50-iteration continuous top-k; emits compact (idx, x*kh) for kh > 1e-5.
// ---------------------------------------------------------------------------
__global__ __launch_bounds__(512)
void topk_kernel(const float* __restrict__ w_in, const float* __restrict__ noise,
                 const float* __restrict__ x,
                 float* __restrict__ spv, int* __restrict__ spi, int* __restrict__ spc)
{
    const int row = blockIdx.x;
    const int t = threadIdx.x;
    const size_t base = (size_t)row * 5000;
    const int lane = t & 31, wid = t >> 5;

    float wv[10], kh[10], e[10];
#pragma unroll
    for (int i = 0; i < 10; i++) {
        const int j = t + i * 512;
        kh[i] = 0.f;
        if (j < 5000) {
            float u = noise[base + j] + 1e-30f;
            wv[i] = w_in[base + j] + __logf(-__logf(u));
        } else {
            wv[i] = -3.0e38f;
        }
    }

    __shared__ float red[16];
    __shared__ float bc;
    __shared__ int s_cnt;
    if (t == 0) s_cnt = 0;

    for (int it = 0; it < 50; it++) {
        float m = wv[0];
#pragma unroll
        for (int i = 1; i < 10; i++) m = fmaxf(m, wv[i]);
#pragma unroll
        for (int o = 16; o > 0; o >>= 1) m = fmaxf(m, __shfl_xor_sync(0xffffffffu, m, o));
        if (lane == 0) red[wid] = m;
        __syncthreads();
        if (t == 0) {
            float mm = red[0];
            for (int k = 1; k < 16; k++) mm = fmaxf(mm, red[k]);
            bc = mm;
        }
        __syncthreads();
        m = bc;
        const float thresh = m - 3.0f;

        float s = 0.f;
#pragma unroll
        for (int i = 0; i < 10; i++) {
            e[i] = 0.f;
            if (__any_sync(0xffffffffu, wv[i] >= thresh)) {
                if (wv[i] >= thresh) {
                    float ee = __expf((wv[i] - m) * 10.0f);
                    e[i] = ee;
                    s += ee;
                }
            }
        }
#pragma unroll
        for (int o = 16; o > 0; o >>= 1) s += __shfl_xor_sync(0xffffffffu, s, o);
        if (lane == 0) red[wid] = s;
        __syncthreads();
        if (t == 0) {
            float ss = red[0];
            for (int k = 1; k < 16; k++) ss += red[k];
            bc = ss;
        }
        __syncthreads();
        const float inv = 1.0f / bc;

#pragma unroll
        for (int i = 0; i < 10; i++) {
            if (__any_sync(0xffffffffu, e[i] > 0.f)) {
                if (e[i] > 0.f) {
                    float oh = e[i] * inv;
                    kh[i] += oh;
                    float mk = fmaxf(1.0f - oh, 1e-30f);
                    if (mk < 1.0f) wv[i] += __logf(mk);
                }
            }
        }
    }

    __syncthreads();
    const size_t sb = (size_t)row * SPCAP;
#pragma unroll
    for (int i = 0; i < 10; i++) {
        const int j = t + i * 512;
        if (j < 5000 && kh[i] > 1e-5f) {
            int p = atomicAdd(&s_cnt, 1);
            if (p < SPCAP) {
                spi[sb + p] = j;
                spv[sb + p] = x[base + j] * kh[i];
            }
        }
    }
    __syncthreads();
    if (t == 0) spc[row] = min(s_cnt, SPCAP);
}

// ---------------------------------------------------------------------------
// Sparse h1 = leaky(xm @ enc_w1 + b)
// ---------------------------------------------------------------------------
__global__ __launch_bounds__(256)
void spmm_kernel(const float* __restrict__ spv, const int* __restrict__ spi,
                 const int* __restrict__ spc,
                 const float* __restrict__ W, const float* __restrict__ bias,
                 float* __restrict__ out)
{
    const int row = blockIdx.x;
    const int t = threadIdx.x;
    const int cnt = spc[row];
    const int col = t * 4;
    const size_t sb = (size_t)row * SPCAP;

    float ax = 0.f, ay = 0.f, az = 0.f, aw = 0.f;
    __shared__ float sv[256];
    __shared__ int   si[256];

    for (int s0 = 0; s0 < cnt; s0 += 256) {
        const int n = min(256, cnt - s0);
        if (t < n) { sv[t] = spv[sb + s0 + t]; si[t] = spi[sb + s0 + t]; }
        __syncthreads();
        int s = 0;
        for (; s + 4 <= n; s += 4) {
            float4 w0 = *(const float4*)&W[(size_t)si[s + 0] * 1024 + col];
            float4 w1 = *(const float4*)&W[(size_t)si[s + 1] * 1024 + col];
            float4 w2 = *(const float4*)&W[(size_t)si[s + 2] * 1024 + col];
            float4 w3 = *(const float4*)&W[(size_t)si[s + 3] * 1024 + col];
            float v0 = sv[s + 0], v1 = sv[s + 1], v2 = sv[s + 2], v3 = sv[s + 3];
            ax = fmaf(v0, w0.x, ax); ay = fmaf(v0, w0.y, ay); az = fmaf(v0, w0.z, az); aw = fmaf(v0, w0.w, aw);
            ax = fmaf(v1, w1.x, ax); ay = fmaf(v1, w1.y, ay); az = fmaf(v1, w1.z, az); aw = fmaf(v1, w1.w, aw);
            ax = fmaf(v2, w2.x, ax); ay = fmaf(v2, w2.y, ay); az = fmaf(v2, w2.z, az); aw = fmaf(v2, w2.w, aw);
            ax = fmaf(v3, w3.x, ax); ay = fmaf(v3, w3.y, ay); az = fmaf(v3, w3.z, az); aw = fmaf(v3, w3.w, aw);
        }
        for (; s < n; s++) {
            float4 w0 = *(const float4*)&W[(size_t)si[s] * 1024 + col];
            float v0 = sv[s];
            ax = fmaf(v0, w0.x, ax); ay = fmaf(v0, w0.y, ay); az = fmaf(v0, w0.z, az); aw = fmaf(v0, w0.w, aw);
        }
        __syncthreads();
    }

    float4 b4 = *(const float4*)&bias[col];
    float4 o;
    o.x = ax + b4.x; o.y = ay + b4.y; o.z = az + b4.z; o.w = aw + b4.w;
    o.x = o.x > 0.f ? o.x : 0.01f * o.x;
    o.y = o.y > 0.f ? o.y : 0.01f * o.y;
    o.z = o.z > 0.f ? o.z : 0.01f * o.z;
    o.w = o.w > 0.f ? o.w : 0.01f * o.w;
    *(float4*)&out[(size_t)row * 1024 + col] = o;
}

// ---------------------------------------------------------------------------
__global__ void reparam_kernel(const float* __restrict__ mu, const float* __restrict__ lv,
                               const float* __restrict__ eps, float* __restrict__ z)
{
    const int i = blockIdx.x * 256 + threadIdx.x;
    if (i < 4096 * 64) z[i] = fmaf(eps[i], __expf(0.5f * lv[i]), mu[i]);
}

// ---------------------------------------------------------------------------
extern "C" void kernel_launch(void* const* d_in, const int* in_sizes, int n_in,
                              void* d_out, int out_size)
{
    const float* x     = (const float*)d_in[0];
    const float* noise = (const float*)d_in[1];
    const float* eps   = (const float*)d_in[2];
    const float* wc_w1 = (const float*)d_in[3];
    const float* wc_b1 = (const float*)d_in[4];
    const float* bn_g  = (const float*)d_in[5];
    const float* bn_b  = (const float*)d_in[6];
    const float* wc_w2 = (const float*)d_in[7];
    const float* wc_b2 = (const float*)d_in[8];
    const float* e_w1  = (const float*)d_in[9];
    const float* e_b1  = (const float*)d_in[10];
    const float* e_w2  = (const float*)d_in[11];
    const float* e_b2  = (const float*)d_in[12];
    const float* e_w3  = (const float*)d_in[13];
    const float* e_b3  = (const float*)d_in[14];
    const float* e_w4  = (const float*)d_in[15];
    const float* e_b4  = (const float*)d_in[16];
    const float* m_w   = (const float*)d_in[17];
    const float* m_b   = (const float*)d_in[18];
    const float* lvw   = (const float*)d_in[19];
    const float* lvb   = (const float*)d_in[20];
    const float* d_w1  = (const float*)d_in[21];
    const float* d_b1  = (const float*)d_in[22];
    const float* d_w2  = (const float*)d_in[23];
    const float* d_b2  = (const float*)d_in[24];

    float* out     = (float*)d_out;
    float* out_mux = out;
    float* out_mu  = out + (size_t)4096 * 5000;
    float* out_lv  = out_mu + (size_t)4096 * 64;

    float *h, *w, *h1, *h2, *h3, *z, *dh, *mean, *rstd, *spv;
    int *spi, *spc;
    cudaGetSymbolAddress((void**)&h,    g_h);
    cudaGetSymbolAddress((void**)&w,    g_w);
    cudaGetSymbolAddress((void**)&h1,   g_h1);
    cudaGetSymbolAddress((void**)&h2,   g_h2);
    cudaGetSymbolAddress((void**)&h3,   g_h3);
    cudaGetSymbolAddress((void**)&z,    g_z);
    cudaGetSymbolAddress((void**)&dh,   g_dh);
    cudaGetSymbolAddress((void**)&mean, g_mean);
    cudaGetSymbolAddress((void**)&rstd, g_rstd);
    cudaGetSymbolAddress((void**)&spv,  g_spv);
    cudaGetSymbolAddress((void**)&spi,  g_spi);
    cudaGetSymbolAddress((void**)&spc,  g_spc);

    cudaFuncSetAttribute(mma_gemm<EPI_NONE>,    cudaFuncAttributeMaxDynamicSharedMemorySize, MMA_SMEM);
    cudaFuncSetAttribute(mma_gemm<EPI_LEAKY>,   cudaFuncAttributeMaxDynamicSharedMemorySize, MMA_SMEM);
    cudaFuncSetAttribute(mma_gemm<EPI_SIGMOID>, cudaFuncAttributeMaxDynamicSharedMemorySize, MMA_SMEM);

    const dim3 blk(256);
    auto grd = [](int N) { return dim3((N + 127) / 128, 32); };   // M = 4096 always

    // weight_creator
    mma_gemm<EPI_NONE><<<grd(512), blk, MMA_SMEM>>>(x, wc_w1, wc_b1, h, 4096, 512, 5000);
    bn_stats_kernel<<<16, dim3(32, 8)>>>(h, mean, rstd);
    bn_apply_kernel<<<(4096 * 512 + 255) / 256, 256>>>(h, mean, rstd, bn_g, bn_b);
    mma_gemm<EPI_NONE><<<grd(5000), blk, MMA_SMEM>>>(h, wc_w2, wc_b2, w, 4096, 5000, 512);

    // gumbel + 50-step continuous top-k -> compact sparse xm
    topk_kernel<<<4096, 512>>>(w, noise, x, spv, spi, spc);

    // encoder (layer 1 sparse, rest tensor-core)
    spmm_kernel<<<4096, 256>>>(spv, spi, spc, e_w1, e_b1, h1);
    mma_gemm<EPI_LEAKY><<<grd(512), blk, MMA_SMEM>>>(h1, e_w2, e_b2, h2, 4096, 512, 1024);
    mma_gemm<EPI_LEAKY><<<grd(512), blk, MMA_SMEM>>>(h2, e_w3, e_b3, h3, 4096, 512, 512);
    mma_gemm<EPI_LEAKY><<<grd(512), blk, MMA_SMEM>>>(h3, e_w4, e_b4, h, 4096, 512, 512);
    mma_gemm<EPI_NONE><<<grd(64), blk, MMA_SMEM>>>(h, m_w, m_b, out_mu, 4096, 64, 512);
    mma_gemm<EPI_NONE><<<grd(64), blk, MMA_SMEM>>>(h, lvw, lvb, out_lv, 4096, 64, 512);

    // reparameterize + decoder
    reparam_kernel<<<(4096 * 64 + 255) / 256, 256>>>(out_mu, out_lv, eps, z);
    mma_gemm<EPI_LEAKY><<<grd(1024), blk, MMA_SMEM>>>(z, d_w1, d_b1, dh, 4096, 1024, 64);
    mma_gemm<EPI_SIGMOID><<<grd(5000), blk, MMA_SMEM>>>(dh, d_w2, d_b2, out_mux, 4096, 5000, 1024);
}

// round 11
// speedup vs baseline: 1.6595x; 1.0492x over previous
#include <cuda_runtime.h>
#include <cuda_bf16.h>

typedef unsigned int u32;
typedef unsigned long long u64;

// ---------------------------------------------------------------------------
// VAE_Gumbel R11 (= R9 resubmit; broker timeouts):
// mma.sync bf16x3 GEMM, 2 CTAs/SM (<=128 regs), x4.trans B-fragment loads.
// B=4096, D=5000, H=512, Z=64.
// ---------------------------------------------------------------------------

#define SPCAP 2048
enum { EPI_NONE = 0, EPI_LEAKY = 2, EPI_SIGMOID = 3 };

#define AST 72    // A smem row stride (bf16), 144B -> conflict-free ldmatrix
#define BST 136   // B smem row stride (bf16), 272B -> conflict-free

__device__ __forceinline__ u32 smem_u32(const void* p) {
    u32 a;
    asm("{ .reg .u64 t; cvta.to.shared.u64 t, %1; cvt.u32.u64 %0, t; }"
        : "=r"(a) : "l"(p));
    return a;
}

__device__ __forceinline__ void ldsm_x4(u32& r0, u32& r1, u32& r2, u32& r3, u32 addr) {
    asm volatile("ldmatrix.sync.aligned.m8n8.x4.shared.b16 {%0,%1,%2,%3}, [%4];"
                 : "=r"(r0), "=r"(r1), "=r"(r2), "=r"(r3) : "r"(addr));
}
__device__ __forceinline__ void ldsm_x4t(u32& r0, u32& r1, u32& r2, u32& r3, u32 addr) {
    asm volatile("ldmatrix.sync.aligned.m8n8.x4.trans.shared.b16 {%0,%1,%2,%3}, [%4];"
                 : "=r"(r0), "=r"(r1), "=r"(r2), "=r"(r3) : "r"(addr));
}
__device__ __forceinline__ void mma_bf16(float* d, const u32* a, u32 b0, u32 b1) {
    asm volatile("mma.sync.aligned.m16n8k16.row.col.f32.bf16.bf16.f32 "
                 "{%0,%1,%2,%3}, {%4,%5,%6,%7}, {%8,%9}, {%0,%1,%2,%3};"
                 : "+f"(d[0]), "+f"(d[1]), "+f"(d[2]), "+f"(d[3])
                 : "r"(a[0]), "r"(a[1]), "r"(a[2]), "r"(a[3]), "r"(b0), "r"(b1));
}

__device__ __forceinline__ u64 pack4bf(float v0, float v1, float v2, float v3,
                                       u64& lo_out) {
    __nv_bfloat16 h0 = __float2bfloat16(v0);
    __nv_bfloat16 h1 = __float2bfloat16(v1);
    __nv_bfloat16 h2 = __float2bfloat16(v2);
    __nv_bfloat16 h3 = __float2bfloat16(v3);
    __nv_bfloat16 l0 = __float2bfloat16(v0 - __bfloat162float(h0));
    __nv_bfloat16 l1 = __float2bfloat16(v1 - __bfloat162float(h1));
    __nv_bfloat16 l2 = __float2bfloat16(v2 - __bfloat162float(h2));
    __nv_bfloat16 l3 = __float2bfloat16(v3 - __bfloat162float(h3));
    lo_out = (u64)*(unsigned short*)&l0 | ((u64)*(unsigned short*)&l1 << 16)
           | ((u64)*(unsigned short*)&l2 << 32) | ((u64)*(unsigned short*)&l3 << 48);
    return (u64)*(unsigned short*)&h0 | ((u64)*(unsigned short*)&h1 << 16)
         | ((u64)*(unsigned short*)&h2 << 32) | ((u64)*(unsigned short*)&h3 << 48);
}

// ---------------------------------------------------------------------------
// bf16x3 split tensor-core GEMM: C[M,N] = act(A[M,K] @ B[K,N] + bias)
// Tile 128x128, K chunk 64, 8 warps (4x2), warp tile 32x64.
// ---------------------------------------------------------------------------
template <int EPI>
__global__ __launch_bounds__(256, 2)
void mma_gemm(const float* __restrict__ A, const float* __restrict__ B,
              const float* __restrict__ bias, float* __restrict__ C,
              int M, int N, int K)
{
    extern __shared__ __nv_bfloat16 smem[];
    __nv_bfloat16* Ash_h = smem;                       // [128][AST]
    __nv_bfloat16* Ash_l = Ash_h + 128 * AST;
    __nv_bfloat16* Bsh_h = Ash_l + 128 * AST;          // [64][BST]
    __nv_bfloat16* Bsh_l = Bsh_h + 64 * BST;

    const int tid = threadIdx.x, lane = tid & 31, wid = tid >> 5;
    const int wm = (wid & 3) * 32;
    const int wn = (wid >> 2) * 64;
    const int row0 = blockIdx.y * 128, n0 = blockIdx.x * 128;

    const u32 aBase = smem_u32(Ash_h);
    const u32 alBase = smem_u32(Ash_l);
    const u32 bBase = smem_u32(Bsh_h);
    const u32 blBase = smem_u32(Bsh_l);

    float acc[2][8][4];
#pragma unroll
    for (int i = 0; i < 2; i++)
#pragma unroll
        for (int j = 0; j < 8; j++)
#pragma unroll
            for (int q = 0; q < 4; q++) acc[i][j][q] = 0.f;

    const int ar = tid >> 1;
    const int ak = (tid & 1) * 4;
    const int bk = tid >> 2;
    const int bn = (tid & 3) * 4;

    const int lm15 = lane & 15;
    const int lm16 = (lane >> 4) * 8;

    const int nchunks = (K + 63) / 64;
    for (int ch = 0; ch < nchunks; ch++) {
        const int k0 = ch * 64;
        __syncthreads();

        // ---- stage A [128 x 64] hi/lo ----
        {
            const float* Ap = A + (size_t)(row0 + ar) * K + k0 + ak;
#pragma unroll
            for (int j = 0; j < 8; j++) {
                const int koff = ak + 8 * j;
                float4 v = (k0 + koff < K) ? *(const float4*)(Ap + 8 * j)
                                           : make_float4(0.f, 0.f, 0.f, 0.f);
                u64 lo;
                u64 hi = pack4bf(v.x, v.y, v.z, v.w, lo);
                const int off = ar * AST + koff;
                *(u64*)(Ash_h + off) = hi;
                *(u64*)(Ash_l + off) = lo;
            }
        }
        // ---- stage B [64 x 128] hi/lo ----
        {
            const float* Bp = B + (size_t)(k0 + bk) * N + n0 + bn;
            const bool kval = (k0 + bk) < K;
#pragma unroll
            for (int j = 0; j < 8; j++) {
                const int noff = bn + 16 * j;
                float4 v = (kval && (n0 + noff) < N) ? *(const float4*)(Bp + 16 * j)
                                                     : make_float4(0.f, 0.f, 0.f, 0.f);
                u64 lo;
                u64 hi = pack4bf(v.x, v.y, v.z, v.w, lo);
                const int off = bk * BST + noff;
                *(u64*)(Bsh_h + off) = hi;
                *(u64*)(Bsh_l + off) = lo;
            }
        }
        __syncthreads();

        // ---- 4 x k16 MMA steps ----
#pragma unroll
        for (int ks = 0; ks < 4; ks++) {
            u32 afh[2][4], afl[2][4];
#pragma unroll
            for (int mi = 0; mi < 2; mi++) {
                const u32 aoff = (u32)((wm + mi * 16 + lm15) * AST + ks * 16 + lm16) * 2;
                ldsm_x4(afh[mi][0], afh[mi][1], afh[mi][2], afh[mi][3], aBase + aoff);
                ldsm_x4(afl[mi][0], afl[mi][1], afl[mi][2], afl[mi][3], alBase + aoff);
            }
            // B: x4.trans loads two n8 tiles at once; loop pairs to keep regs low
#pragma unroll
            for (int np = 0; np < 4; np++) {
                const u32 boff = (u32)((ks * 16 + lm15) * BST + wn + np * 16 + lm16) * 2;
                u32 h0, h1, h2, h3, l0, l1, l2, l3;
                ldsm_x4t(h0, h1, h2, h3, bBase + boff);
                ldsm_x4t(l0, l1, l2, l3, blBase + boff);
#pragma unroll
                for (int mi = 0; mi < 2; mi++) {
                    mma_bf16(acc[mi][2 * np],     afh[mi], h0, h1);
                    mma_bf16(acc[mi][2 * np],     afh[mi], l0, l1);
                    mma_bf16(acc[mi][2 * np],     afl[mi], h0, h1);
                    mma_bf16(acc[mi][2 * np + 1], afh[mi], h2, h3);
                    mma_bf16(acc[mi][2 * np + 1], afh[mi], l2, l3);
                    mma_bf16(acc[mi][2 * np + 1], afl[mi], h2, h3);
                }
            }
        }
    }

    // ---- epilogue ----
    const int rg = lane >> 2;
    const int cp = (lane & 3) * 2;
#pragma unroll
    for (int mi = 0; mi < 2; mi++) {
#pragma unroll
        for (int ni = 0; ni < 8; ni++) {
            const int c = n0 + wn + ni * 8 + cp;
            if (c < N) {
                const float b0 = bias[c], b1 = bias[c + 1];
#pragma unroll
                for (int half = 0; half < 2; half++) {
                    const int r = row0 + wm + mi * 16 + rg + half * 8;
                    float v0 = acc[mi][ni][2 * half]     + b0;
                    float v1 = acc[mi][ni][2 * half + 1] + b1;
                    if (EPI == EPI_LEAKY) {
                        v0 = v0 > 0.f ? v0 : 0.01f * v0;
                        v1 = v1 > 0.f ? v1 : 0.01f * v1;
                    }
                    if (EPI == EPI_SIGMOID) {
                        v0 = 1.0f / (1.0f + __expf(-v0));
                        v1 = 1.0f / (1.0f + __expf(-v1));
                    }
                    C[(size_t)r * N + c]     = v0;
                    C[(size_t)r * N + c + 1] = v1;
                }
            }
        }
    }
}

#define MMA_SMEM ((2 * 128 * AST + 2 * 64 * BST) * (int)sizeof(__nv_bfloat16))

// ---------------------------------------------------------------------------
// Scratch globals
// ---------------------------------------------------------------------------
__device__ float g_h  [4096u * 512];
__device__ float g_w  [4096u * 5000];
__device__ float g_h1 [4096u * 1024];
__device__ float g_h2 [4096u * 512];
__device__ float g_h3 [4096u * 512];
__device__ float g_z  [4096u * 64];
__device__ float g_dh [4096u * 1024];
__device__ float g_mean[512];
__device__ float g_rstd[512];
__device__ float g_spv[4096u * SPCAP];
__device__ int   g_spi[4096u * SPCAP];
__device__ int   g_spc[4096];

// ---------------------------------------------------------------------------
__global__ void bn_stats_kernel(const float* __restrict__ h,
                                float* __restrict__ mean, float* __restrict__ rstd)
{
    const int col = blockIdx.x * 32 + threadIdx.x;
    float s = 0.f, s2 = 0.f;
    for (int r = threadIdx.y; r < 4096; r += 8) {
        float v = h[(size_t)r * 512 + col];
        s += v; s2 += v * v;
    }
    __shared__ float sh[8][32];
    __shared__ float sh2[8][32];
    sh[threadIdx.y][threadIdx.x]  = s;
    sh2[threadIdx.y][threadIdx.x] = s2;
    __syncthreads();
    if (threadIdx.y == 0) {
        for (int y = 1; y < 8; y++) { s += sh[y][threadIdx.x]; s2 += sh2[y][threadIdx.x]; }
        float m   = s * (1.f / 4096.f);
        float var = s2 * (1.f / 4096.f) - m * m;
        mean[col] = m;
        rstd[col] = rsqrtf(var + 1e-5f);
    }
}

__global__ void bn_apply_kernel(float* __restrict__ h,
                                const float* __restrict__ mean, const float* __restrict__ rstd,
                                const float* __restrict__ g, const float* __restrict__ b)
{
    const int i = blockIdx.x * 256 + threadIdx.x;
    if (i < 4096 * 512) {
        const int c = i & 511;
        float v = (h[i] - mean[c]) * rstd[c] * g[c] + b[c];
        h[i] = fmaxf(v, 0.f);
    }
}

// ---------------------------------------------------------------------------
// 50-iteration continuous top-k; emits compact (idx, x*kh) for kh > 1e-5.
// ---------------------------------------------------------------------------
__global__ __launch_bounds__(512)
void topk_kernel(const float* __restrict__ w_in, const float* __restrict__ noise,
                 const float* __restrict__ x,
                 float* __restrict__ spv, int* __restrict__ spi, int* __restrict__ spc)
{
    const int row = blockIdx.x;
    const int t = threadIdx.x;
    const size_t base = (size_t)row * 5000;
    const int lane = t & 31, wid = t >> 5;

    float wv[10], kh[10], e[10];
#pragma unroll
    for (int i = 0; i < 10; i++) {
        const int j = t + i * 512;
        kh[i] = 0.f;
        if (j < 5000) {
            float u = noise[base + j] + 1e-30f;
            wv[i] = w_in[base + j] + __logf(-__logf(u));
        } else {
            wv[i] = -3.0e38f;
        }
    }

    __shared__ float red[16];
    __shared__ float bc;
    __shared__ int s_cnt;
    if (t == 0) s_cnt = 0;

    for (int it = 0; it < 50; it++) {
        float m = wv[0];
#pragma unroll
        for (int i = 1; i < 10; i++) m = fmaxf(m, wv[i]);
#pragma unroll
        for (int o = 16; o > 0; o >>= 1) m = fmaxf(m, __shfl_xor_sync(0xffffffffu, m, o));
        if (lane == 0) red[wid] = m;
        __syncthreads();
        if (t == 0) {
            float mm = red[0];
            for (int k = 1; k < 16; k++) mm = fmaxf(mm, red[k]);
            bc = mm;
        }
        __syncthreads();
        m = bc;
        const float thresh = m - 3.0f;

        float s = 0.f;
#pragma unroll
        for (int i = 0; i < 10; i++) {
            e[i] = 0.f;
            if (__any_sync(0xffffffffu, wv[i] >= thresh)) {
                if (wv[i] >= thresh) {
                    float ee = __expf((wv[i] - m) * 10.0f);
                    e[i] = ee;
                    s += ee;
                }
            }
        }
#pragma unroll
        for (int o = 16; o > 0; o >>= 1) s += __shfl_xor_sync(0xffffffffu, s, o);
        if (lane == 0) red[wid] = s;
        __syncthreads();
        if (t == 0) {
            float ss = red[0];
            for (int k = 1; k < 16; k++) ss += red[k];
            bc = ss;
        }
        __syncthreads();
        const float inv = 1.0f / bc;

#pragma unroll
        for (int i = 0; i < 10; i++) {
            if (__any_sync(0xffffffffu, e[i] > 0.f)) {
                if (e[i] > 0.f) {
                    float oh = e[i] * inv;
                    kh[i] += oh;
                    float mk = fmaxf(1.0f - oh, 1e-30f);
                    if (mk < 1.0f) wv[i] += __logf(mk);
                }
            }
        }
    }

    __syncthreads();
    const size_t sb = (size_t)row * SPCAP;
#pragma unroll
    for (int i = 0; i < 10; i++) {
        const int j = t + i * 512;
        if (j < 5000 && kh[i] > 1e-5f) {
            int p = atomicAdd(&s_cnt, 1);
            if (p < SPCAP) {
                spi[sb + p] = j;
                spv[sb + p] = x[base + j] * kh[i];
            }
        }
    }
    __syncthreads();
    if (t == 0) spc[row] = min(s_cnt, SPCAP);
}

// ---------------------------------------------------------------------------
// Sparse h1 = leaky(xm @ enc_w1 + b)
// ---------------------------------------------------------------------------
__global__ __launch_bounds__(256)
void spmm_kernel(const float* __restrict__ spv, const int* __restrict__ spi,
                 const int* __restrict__ spc,
                 const float* __restrict__ W, const float* __restrict__ bias,
                 float* __restrict__ out)
{
    const int row = blockIdx.x;
    const int t = threadIdx.x;
    const int cnt = spc[row];
    const int col = t * 4;
    const size_t sb = (size_t)row * SPCAP;

    float ax = 0.f, ay = 0.f, az = 0.f, aw = 0.f;
    __shared__ float sv[256];
    __shared__ int   si[256];

    for (int s0 = 0; s0 < cnt; s0 += 256) {
        const int n = min(256, cnt - s0);
        if (t < n) { sv[t] = spv[sb + s0 + t]; si[t] = spi[sb + s0 + t]; }
        __syncthreads();
        int s = 0;
        for (; s + 4 <= n; s += 4) {
            float4 w0 = *(const float4*)&W[(size_t)si[s + 0] * 1024 + col];
            float4 w1 = *(const float4*)&W[(size_t)si[s + 1] * 1024 + col];
            float4 w2 = *(const float4*)&W[(size_t)si[s + 2] * 1024 + col];
            float4 w3 = *(const float4*)&W[(size_t)si[s + 3] * 1024 + col];
            float v0 = sv[s + 0], v1 = sv[s + 1], v2 = sv[s + 2], v3 = sv[s + 3];
            ax = fmaf(v0, w0.x, ax); ay = fmaf(v0, w0.y, ay); az = fmaf(v0, w0.z, az); aw = fmaf(v0, w0.w, aw);
            ax = fmaf(v1, w1.x, ax); ay = fmaf(v1, w1.y, ay); az = fmaf(v1, w1.z, az); aw = fmaf(v1, w1.w, aw);
            ax = fmaf(v2, w2.x, ax); ay = fmaf(v2, w2.y, ay); az = fmaf(v2, w2.z, az); aw = fmaf(v2, w2.w, aw);
            ax = fmaf(v3, w3.x, ax); ay = fmaf(v3, w3.y, ay); az = fmaf(v3, w3.z, az); aw = fmaf(v3, w3.w, aw);
        }
        for (; s < n; s++) {
            float4 w0 = *(const float4*)&W[(size_t)si[s] * 1024 + col];
            float v0 = sv[s];
            ax = fmaf(v0, w0.x, ax); ay = fmaf(v0, w0.y, ay); az = fmaf(v0, w0.z, az); aw = fmaf(v0, w0.w, aw);
        }
        __syncthreads();
    }

    float4 b4 = *(const float4*)&bias[col];
    float4 o;
    o.x = ax + b4.x; o.y = ay + b4.y; o.z = az + b4.z; o.w = aw + b4.w;
    o.x = o.x > 0.f ? o.x : 0.01f * o.x;
    o.y = o.y > 0.f ? o.y : 0.01f * o.y;
    o.z = o.z > 0.f ? o.z : 0.01f * o.z;
    o.w = o.w > 0.f ? o.w : 0.01f * o.w;
    *(float4*)&out[(size_t)row * 1024 + col] = o;
}

// ---------------------------------------------------------------------------
__global__ void reparam_kernel(const float* __restrict__ mu, const float* __restrict__ lv,
                               const float* __restrict__ eps, float* __restrict__ z)
{
    const int i = blockIdx.x * 256 + threadIdx.x;
    if (i < 4096 * 64) z[i] = fmaf(eps[i], __expf(0.5f * lv[i]), mu[i]);
}

// ---------------------------------------------------------------------------
extern "C" void kernel_launch(void* const* d_in, const int* in_sizes, int n_in,
                              void* d_out, int out_size)
{
    const float* x     = (const float*)d_in[0];
    const float* noise = (const float*)d_in[1];
    const float* eps   = (const float*)d_in[2];
    const float* wc_w1 = (const float*)d_in[3];
    const float* wc_b1 = (const float*)d_in[4];
    const float* bn_g  = (const float*)d_in[5];
    const float* bn_b  = (const float*)d_in[6];
    const float* wc_w2 = (const float*)d_in[7];
    const float* wc_b2 = (const float*)d_in[8];
    const float* e_w1  = (const float*)d_in[9];
    const float* e_b1  = (const float*)d_in[10];
    const float* e_w2  = (const float*)d_in[11];
    const float* e_b2  = (const float*)d_in[12];
    const float* e_w3  = (const float*)d_in[13];
    const float* e_b3  = (const float*)d_in[14];
    const float* e_w4  = (const float*)d_in[15];
    const float* e_b4  = (const float*)d_in[16];
    const float* m_w   = (const float*)d_in[17];
    const float* m_b   = (const float*)d_in[18];
    const float* lvw   = (const float*)d_in[19];
    const float* lvb   = (const float*)d_in[20];
    const float* d_w1  = (const float*)d_in[21];
    const float* d_b1  = (const float*)d_in[22];
    const float* d_w2  = (const float*)d_in[23];
    const float* d_b2  = (const float*)d_in[24];

    float* out     = (float*)d_out;
    float* out_mux = out;
    float* out_mu  = out + (size_t)4096 * 5000;
    float* out_lv  = out_mu + (size_t)4096 * 64;

    float *h, *w, *h1, *h2, *h3, *z, *dh, *mean, *rstd, *spv;
    int *spi, *spc;
    cudaGetSymbolAddress((void**)&h,    g_h);
    cudaGetSymbolAddress((void**)&w,    g_w);
    cudaGetSymbolAddress((void**)&h1,   g_h1);
    cudaGetSymbolAddress((void**)&h2,   g_h2);
    cudaGetSymbolAddress((void**)&h3,   g_h3);
    cudaGetSymbolAddress((void**)&z,    g_z);
    cudaGetSymbolAddress((void**)&dh,   g_dh);
    cudaGetSymbolAddress((void**)&mean, g_mean);
    cudaGetSymbolAddress((void**)&rstd, g_rstd);
    cudaGetSymbolAddress((void**)&spv,  g_spv);
    cudaGetSymbolAddress((void**)&spi,  g_spi);
    cudaGetSymbolAddress((void**)&spc,  g_spc);

    cudaFuncSetAttribute(mma_gemm<EPI_NONE>,    cudaFuncAttributeMaxDynamicSharedMemorySize, MMA_SMEM);
    cudaFuncSetAttribute(mma_gemm<EPI_LEAKY>,   cudaFuncAttributeMaxDynamicSharedMemorySize, MMA_SMEM);
    cudaFuncSetAttribute(mma_gemm<EPI_SIGMOID>, cudaFuncAttributeMaxDynamicSharedMemorySize, MMA_SMEM);

    const dim3 blk(256);
    auto grd = [](int N) { return dim3((N + 127) / 128, 32); };   // M = 4096 always

    // weight_creator
    mma_gemm<EPI_NONE><<<grd(512), blk, MMA_SMEM>>>(x, wc_w1, wc_b1, h, 4096, 512, 5000);
    bn_stats_kernel<<<16, dim3(32, 8)>>>(h, mean, rstd);
    bn_apply_kernel<<<(4096 * 512 + 255) / 256, 256>>>(h, mean, rstd, bn_g, bn_b);
    mma_gemm<EPI_NONE><<<grd(5000), blk, MMA_SMEM>>>(h, wc_w2, wc_b2, w, 4096, 5000, 512);

    // gumbel + 50-step continuous top-k -> compact sparse xm
    topk_kernel<<<4096, 512>>>(w, noise, x, spv, spi, spc);

    // encoder (layer 1 sparse, rest tensor-core)
    spmm_kernel<<<4096, 256>>>(spv, spi, spc, e_w1, e_b1, h1);
    mma_gemm<EPI_LEAKY><<<grd(512), blk, MMA_SMEM>>>(h1, e_w2, e_b2, h2, 4096, 512, 1024);
    mma_gemm<EPI_LEAKY><<<grd(512), blk, MMA_SMEM>>>(h2, e_w3, e_b3, h3, 4096, 512, 512);
    mma_gemm<EPI_LEAKY><<<grd(512), blk, MMA_SMEM>>>(h3, e_w4, e_b4, h, 4096, 512, 512);
    mma_gemm<EPI_NONE><<<grd(64), blk, MMA_SMEM>>>(h, m_w, m_b, out_mu, 4096, 64, 512);
    mma_gemm<EPI_NONE><<<grd(64), blk, MMA_SMEM>>>(h, lvw, lvb, out_lv, 4096, 64, 512);

    // reparameterize + decoder
    reparam_kernel<<<(4096 * 64 + 255) / 256, 256>>>(out_mu, out_lv, eps, z);
    mma_gemm<EPI_LEAKY><<<grd(1024), blk, MMA_SMEM>>>(z, d_w1, d_b1, dh, 4096, 1024, 64);
    mma_gemm<EPI_SIGMOID><<<grd(5000), blk, MMA_SMEM>>>(dh, d_w2, d_b2, out_mux, 4096, 5000, 1024);
}